// round 14
// baseline (speedup 1.0000x reference)
#include <cuda_runtime.h>
#include <math.h>

#define BATCH 8
#define NCLS 3
#define H 384
#define W 384
#define HW (H*W)
#define NBC 24
#define NWARP 12   // 384/32 (k2 warps)
#define NWORD 12   // H/32 mask words per column
#define CT 8       // columns per k1 block
#define R 4        // rows per k2 block
#define RG (H/R)   // 96 row-groups
#define P 32       // fast-path EDT pad/radius
#define SENT2 1046529.0f   // 1023^2

// Scratch (device globals, fully overwritten each launch)
// layout: [b][c][word][j]
__device__ unsigned g_mask[BATCH*3*NWORD*W];
__device__ int      g_pn  [BATCH*3*NWORD*W];   // low16 = prev row (s16), high16 = next row (s16)
__device__ float g_psum_bg[NBC*RG];
__device__ float g_psum_fg[NBC*RG];
__device__ float g_pmax_bg[NBC*RG];
__device__ float g_pmax_fg[NBC*RG];

// ---------------------------------------------------------------------------
// k1: coalesced-load mask builder. Block = (8-col strip, batch), 256 threads
// (2x blocks of round-13 for wave smoothing). Phase A: prefetch 12 strip
// values (MLP=12) -> pad-9 smem. Phase B: warp <-> column (8 warps, 8 cols),
// lane = row-in-word, ballots -> mask smem (stride-9 reads conflict-free,
// gcd(9,32)=1). Phase C: 288 items stride-looped over 256 threads: coalesced
// g_mask stores + prev/next set-row scan.
// ---------------------------------------------------------------------------
__global__ void __launch_bounds__(256) k1_masks(const int* __restrict__ targets, int b0) {
    __shared__ int staged[H][CT + 1];          // pad 9
    __shared__ unsigned msm[3][NWORD][CT];
    const int tid = threadIdx.x;
    const int b = blockIdx.y + b0;
    const int j0 = blockIdx.x * CT;

    // Phase A
    const int r = tid >> 3;        // 0..31 row-within-word
    const int c = tid & 7;         // 0..7 column
    int v[NWORD];
    #pragma unroll
    for (int w = 0; w < NWORD; w++)
        v[w] = targets[b*HW + (w*32 + r)*W + j0 + c];
    #pragma unroll
    for (int w = 0; w < NWORD; w++)
        staged[w*32 + r][c] = v[w];
    __syncthreads();

    // Phase B
    const int ww = tid >> 5, lane = tid & 31;   // 8 warps <-> 8 columns
    #pragma unroll
    for (int w = 0; w < NWORD; w++) {
        int tv = staged[w*32 + lane][ww];
        unsigned b0m = __ballot_sync(0xffffffffu, tv == 0);
        unsigned b1m = __ballot_sync(0xffffffffu, tv == 1);
        if (lane == 0) {
            msm[0][w][ww] = b0m;
            msm[1][w][ww] = b1m;
            msm[2][w][ww] = ~(b0m | b1m);
        }
    }
    __syncthreads();

    // Phase C: 288 items on 256 threads (stride loop covers all)
    for (int t = tid; t < 3*NWORD*CT; t += 256) {
        const int c2  = t / (NWORD*CT);
        const int rem = t % (NWORD*CT);
        const int w2  = rem / CT;
        const int col = rem % CT;
        const int gidx = ((b*3 + c2)*NWORD + w2)*W + j0 + col;
        g_mask[gidx] = msm[c2][w2][col];
        int prev = -2000;
        for (int k = w2 - 1; k >= 0; --k) {
            unsigned m = msm[c2][k][col];
            if (m) { prev = k*32 + 31 - __clz(m); break; }
        }
        int next = 3000;
        for (int k = w2 + 1; k < NWORD; ++k) {
            unsigned m = msm[c2][k][col];
            if (m) { next = k*32 + __ffs(m) - 1; break; }
        }
        g_pn[gidx] = (int)(((unsigned)(prev & 0xffff)) | ((unsigned)next << 16));
    }
}

// ---------------------------------------------------------------------------
// k2: single-barrier fused kernel (round-10 structure, proven; batch offset
// parameter added). Phase 1: all 12 g^2 into padded smem. One sync. Phase 2:
// per-row EDT with per-pixel exit (2 radii/trip), sentinel pads, cold
// fallback. MUFU-minimized epilogue, one block reduction.
// ---------------------------------------------------------------------------
__global__ void __launch_bounds__(384) k2_fused(const float* __restrict__ logits, int b0) {
    __shared__ float sh[3][R][W + 2*P];
    __shared__ float red[NWARP][12];
    const int j = threadIdx.x;
    const int rg = blockIdx.x, b = blockIdx.y + b0;
    const int row0 = rg * R;
    const int w = row0 >> 5;          // rows of this block share one mask word
    const int lane = j & 31, wid = j >> 5;

    // sentinel pads
    if (j < 2*P) {
        const int side = (j < P) ? j : (W + j);
        #pragma unroll
        for (int c = 0; c < 3; c++)
            #pragma unroll
            for (int ri = 0; ri < R; ri++)
                sh[c][ri][side] = SENT2;
    }

    const int mbase = ((b*3)*NWORD + w)*W + j;   // class stride = NWORD*W
    unsigned mw[3];
    int prv[3], nxt[3];
    #pragma unroll
    for (int c = 0; c < 3; c++) {
        mw[c] = g_mask[mbase + c*NWORD*W];
        int pn = g_pn[mbase + c*NWORD*W];
        prv[c] = (int)(short)(pn & 0xffff);
        nxt[c] = pn >> 16;
    }

    // phase 1: all column distances -> smem
    #pragma unroll
    for (int ri = 0; ri < R; ri++) {
        const int row = row0 + ri;
        const int lr = row & 31;                         // uniform
        const unsigned lowmask = 0xffffffffu >> (31 - lr);
        const unsigned himask  = 0xffffffffu << lr;
        #pragma unroll
        for (int c = 0; c < 3; c++) {
            unsigned mlo = mw[c] & lowmask;
            int dfw = mlo ? (lr + __clz(mlo) - 31) : (row - prv[c]);
            unsigned mhi = mw[c] & himask;
            int dbw = mhi ? (__ffs(mhi) - 1 - lr) : (nxt[c] - row);
            int g = min(min(dfw, dbw), 1023);
            sh[c][ri][P + j] = (float)(g * g);
        }
    }
    __syncthreads();   // the only block barrier before the reduction

    float accs[6] = {0,0,0,0,0,0};      // p*dbg, p*dfg per class
    float accm[6] = {0,0,0,0,0,0};      // max d2 bg, max d2 fg per class

    #pragma unroll
    for (int ri = 0; ri < R; ri++) {
        const int row = row0 + ri;
        const float* s0 = &sh[0][ri][P];
        const float* s1 = &sh[1][ri][P];
        const float* s2 = &sh[2][ri][P];
        float b0v = s0[j], b1v = s1[j], b2v = s2[j];
        float bestmax = fmaxf(b0v, fmaxf(b1v, b2v));
        float rf = 1.0f;
        int r = 1;
        while (rf*rf < bestmax && r + 1 <= P) {
            const float rr1 = rf*rf;
            const float rr2 = (rf + 1.0f)*(rf + 1.0f);
            b0v = fminf(b0v, fminf(s0[j-r],   s0[j+r])   + rr1);
            b1v = fminf(b1v, fminf(s1[j-r],   s1[j+r])   + rr1);
            b2v = fminf(b2v, fminf(s2[j-r],   s2[j+r])   + rr1);
            b0v = fminf(b0v, fminf(s0[j-r-1], s0[j+r+1]) + rr2);
            b1v = fminf(b1v, fminf(s1[j-r-1], s1[j+r+1]) + rr2);
            b2v = fminf(b2v, fminf(s2[j-r-1], s2[j+r+1]) + rr2);
            bestmax = fmaxf(b0v, fmaxf(b1v, b2v));
            r += 2; rf += 2.0f;
        }
        while (rf*rf < bestmax && r < W) {
            const float rr = rf*rf;
            const int lo = j - r, hi = j + r;
            if (lo >= 0) {
                b0v = fminf(b0v, s0[lo] + rr);
                b1v = fminf(b1v, s1[lo] + rr);
                b2v = fminf(b2v, s2[lo] + rr);
            }
            if (hi < W) {
                b0v = fminf(b0v, s0[hi] + rr);
                b1v = fminf(b1v, s1[hi] + rr);
                b2v = fminf(b2v, s2[hi] + rr);
            }
            bestmax = fmaxf(b0v, fmaxf(b1v, b2v));
            r++; rf += 1.0f;
        }
        float sb0 = sqrtf(b0v), sb1 = sqrtf(b1v), sb2 = sqrtf(b2v);
        float sf0 = fminf(sb1, sb2);
        float sf1 = fminf(sb0, sb2);
        float sf2 = fminf(sb0, sb1);

        const float* lp = logits + (b*3)*HW + row*W + j;
        float l2v = lp[2*HW];
        float e0 = __expf(lp[0] - l2v), e1 = __expf(lp[HW] - l2v);
        float inv = __fdividef(1.0f, e0 + e1 + 1.0f);
        float p0 = e0*inv, p1 = e1*inv, p2 = inv;

        accs[0] += p0 * sb0;
        accs[1] += p1 * sb1;
        accs[2] += p2 * sb2;
        accs[3] += p0 * sf0;
        accs[4] += p1 * sf1;
        accs[5] += p2 * sf2;
        accm[0] = fmaxf(accm[0], b0v);
        accm[1] = fmaxf(accm[1], b1v);
        accm[2] = fmaxf(accm[2], b2v);
        accm[3] = fmaxf(accm[3], fminf(b1v, b2v));
        accm[4] = fmaxf(accm[4], fminf(b0v, b2v));
        accm[5] = fmaxf(accm[5], fminf(b0v, b1v));
    }

    #pragma unroll
    for (int off = 16; off; off >>= 1) {
        #pragma unroll
        for (int s = 0; s < 6; s++) accs[s] += __shfl_xor_sync(0xffffffffu, accs[s], off);
    }
    #pragma unroll
    for (int s = 0; s < 6; s++)
        accm[s] = __uint_as_float(__reduce_max_sync(0xffffffffu, __float_as_uint(accm[s])));

    if (lane == 0) {
        #pragma unroll
        for (int s = 0; s < 6; s++) { red[wid][s] = accs[s]; red[wid][6+s] = accm[s]; }
    }
    __syncthreads();
    if (threadIdx.x < 12) {
        int s = threadIdx.x;
        float acc = red[0][s];
        #pragma unroll
        for (int ww = 1; ww < NWARP; ww++)
            acc = (s < 6) ? (acc + red[ww][s]) : fmaxf(acc, red[ww][s]);
        int c = s % 3;
        int idx = (b*3 + c) * RG + rg;
        int grp = s / 3;
        if      (grp == 0) g_psum_bg[idx] = acc;
        else if (grp == 1) g_psum_fg[idx] = acc;
        else if (grp == 2) g_pmax_bg[idx] = sqrtf(acc);   // sqrt(max d2) == max d
        else               g_pmax_fg[idx] = sqrtf(acc);
    }
}

// ---------------------------------------------------------------------------
// k3: final reduce. Warp per (b,c) map; gate = (Mbg < 600) <=> mask nonempty.
// ---------------------------------------------------------------------------
__global__ void k3_final(float* out) {
    const int lane = threadIdx.x & 31, bc = threadIdx.x >> 5;   // 24 warps
    double sbg = 0.0, sfg = 0.0;
    float mbg = 0.0f, mfg = 0.0f;
    for (int r = lane; r < RG; r += 32) {
        sbg += (double)g_psum_bg[bc*RG + r];
        sfg += (double)g_psum_fg[bc*RG + r];
        mbg = fmaxf(mbg, g_pmax_bg[bc*RG + r]);
        mfg = fmaxf(mfg, g_pmax_fg[bc*RG + r]);
    }
    #pragma unroll
    for (int off = 16; off; off >>= 1) {
        sbg += __shfl_xor_sync(0xffffffffu, sbg, off);
        sfg += __shfl_xor_sync(0xffffffffu, sfg, off);
        mbg = fmaxf(mbg, __shfl_xor_sync(0xffffffffu, mbg, off));
        mfg = fmaxf(mfg, __shfl_xor_sync(0xffffffffu, mfg, off));
    }
    __shared__ double cs[24];
    if (lane == 0) {
        double contrib = 0.0;
        if (mbg < 600.0f) {   // mask nonempty (empty-map sentinel d >= 1023)
            contrib = sbg / (double)fmaxf(mbg, 1e-12f)
                    - sfg / (double)fmaxf(mfg, 1e-12f);
        }
        cs[bc] = contrib;
    }
    __syncthreads();
    if (threadIdx.x == 0) {
        double s = 0.0;
        #pragma unroll
        for (int k = 0; k < 24; k++) s += cs[k];
        out[0] = (float)(s / (24.0 * (double)HW));
    }
}

extern "C" void kernel_launch(void* const* d_in, const int* in_sizes, int n_in,
                              void* d_out, int out_size) {
    const float* logits  = (const float*)d_in[0];
    const int*   targets = (const int*)d_in[1];

    // Lazily created once on the first (non-captured) correctness call; only
    // record/wait are issued during capture (standard fork/join pattern).
    static cudaStream_t s2 = nullptr;
    static cudaEvent_t eA = nullptr, eB = nullptr;
    if (s2 == nullptr) {
        cudaStreamCreateWithFlags(&s2, cudaStreamNonBlocking);
        cudaEventCreateWithFlags(&eA, cudaEventDisableTiming);
        cudaEventCreateWithFlags(&eB, cudaEventDisableTiming);
    }

    const dim3 g1(W / CT, BATCH/2);
    const dim3 g2(RG, BATCH/2);

    // half A masks on default stream
    k1_masks<<<g1, 256>>>(targets, 0);
    cudaEventRecord(eA, 0);
    // half A fused on s2, overlapping half B masks (+ half B fused) on default
    cudaStreamWaitEvent(s2, eA, 0);
    k2_fused<<<g2, W, 0, s2>>>(logits, 0);
    cudaEventRecord(eB, s2);
    k1_masks<<<g1, 256>>>(targets, BATCH/2);
    k2_fused<<<g2, W>>>(logits, BATCH/2);
    // join and finalize
    cudaStreamWaitEvent(0, eB, 0);
    k3_final<<<1, 24 * 32>>>((float*)d_out);
}